// round 12
// baseline (speedup 1.0000x reference)
#include <cuda_runtime.h>
#include <cuda_fp16.h>
#include <cstdint>

#define T_STEPS 8192
#define HDIM    1024
#define IN_DIM  9
#define GDIM    (4 * HDIM)
#define NC0     52          // layer-0 CTAs: nj<=20, 80 rows = 5 m-tiles
#define NC1     86          // layer-1 CTAs: nj<=12, 48 rows = 3 m-tiles
#define NCTA    (NC0 + NC1)
#define NTHR    512         // 16 warps: warp w owns K range [64w, 64w+64)

typedef unsigned int u32;
typedef unsigned long long u64;

// Persistent device scratch. h stored as pre-split fp16 hi/lo pairs.
__device__ __align__(16) float  g_gx0[(size_t)T_STEPS * GDIM];
__device__ __align__(16) __half g_h0h[(size_t)T_STEPS * HDIM];
__device__ __align__(16) __half g_h0l[(size_t)T_STEPS * HDIM];
__device__ __align__(16) __half g_h1h[(size_t)T_STEPS * HDIM];
__device__ __align__(16) __half g_h1l[(size_t)T_STEPS * HDIM];
__device__ u64 g_ctr[32];                                      // [0]=c0, [16]=c1

// exp-based gates (R8-validated fast path; tanh.approx regressed 3/3 rounds)
__device__ __forceinline__ float fsig(float x) {
    return __fdividef(1.0f, 1.0f + __expf(-x));
}
__device__ __forceinline__ float ftanh_(float x) {
    float a = fabsf(x);
    float e = __expf(-2.0f * a);
    return copysignf(__fdividef(1.0f - e, 1.0f + e), x);
}
__device__ __forceinline__ u64 ld_acquire(const u64* p) {
    u64 v;
    asm volatile("ld.acquire.gpu.global.u64 %0, [%1];" : "=l"(v) : "l"(p) : "memory");
    return v;
}
__device__ __forceinline__ void wait_ge(const u64* p, u64 tgt) {
    while (ld_acquire(p) < tgt) { }
}
__device__ __forceinline__ void red_release(u64* p) {
    asm volatile("red.release.gpu.global.add.u64 [%0], 1;" :: "l"(p) : "memory");
}

__device__ __forceinline__ void mma_one(float* acc, const u32* a, u32 b0, u32 b1) {
    asm volatile(
        "mma.sync.aligned.m16n8k16.row.col.f32.f16.f16.f32 "
        "{%0,%1,%2,%3},{%4,%5,%6,%7},{%8,%9},{%0,%1,%2,%3};"
        : "+f"(acc[0]), "+f"(acc[1]), "+f"(acc[2]), "+f"(acc[3])
        : "r"(a[0]), "r"(a[1]), "r"(a[2]), "r"(a[3]), "r"(b0), "r"(b1));
}

// ---- Persistent A fragments (m16n8k16 row-major A) from fp32 weights.
// Warp w owns K range [64w, 64w+64). Local row lr = jl*4+gate,
// global row R = gate*HDIM + j0 + jl (PyTorch gate order i,f,g,o).
template<int NT>
__device__ __forceinline__ void load_frags(u32 af[][4][4],
                                           const float* __restrict__ W,
                                           int j0, int nrows,
                                           int wid, int gid, int tg)
{
#pragma unroll
    for (int mt = 0; mt < NT; ++mt) {
#pragma unroll
        for (int kc = 0; kc < 4; ++kc) {
            const int k0 = wid * 64 + kc * 16;
#pragma unroll
            for (int i = 0; i < 4; ++i) {
                const int lr = mt * 16 + ((i & 1) ? 8 : 0) + gid;
                const int c  = k0 + 2 * tg + ((i & 2) ? 8 : 0);
                u32 v = 0u;
                if (lr < nrows) {
                    const int jl = lr >> 2, gate = lr & 3;
                    const float2 w2 = *(const float2*)(W +
                        ((size_t)((gate << 10) + j0 + jl) << 10) + c);
                    const __half2 h2 = __floats2half2_rn(w2.x, w2.y);
                    v = *(const u32*)&h2;
                }
                af[mt][kc][i] = v;
            }
        }
    }
}

// acc += A*vh + A*vl (pre-split hi/lo fp16). B col0 = v, cols 1-7 = 0.
template<int NT>
__device__ __forceinline__ void mma_phase(float acc[][4],
                                          const u32 af[][4][4],
                                          const __half* __restrict__ vh,
                                          const __half* __restrict__ vl,
                                          int wid, int gid, int tg)
{
#pragma unroll
    for (int kc = 0; kc < 4; ++kc) {
        u32 bh0 = 0u, bh1 = 0u, bl0 = 0u, bl1 = 0u;
        if (gid == 0) {
            const int k0 = wid * 64 + kc * 16 + 2 * tg;
            bh0 = *(const u32*)(vh + k0);
            bh1 = *(const u32*)(vh + k0 + 8);
            bl0 = *(const u32*)(vl + k0);
            bl1 = *(const u32*)(vl + k0 + 8);
        }
#pragma unroll
        for (int mt = 0; mt < NT; ++mt) {
            mma_one(acc[mt], af[mt][kc], bh0, bh1);
        }
#pragma unroll
        for (int mt = 0; mt < NT; ++mt) {
            mma_one(acc[mt], af[mt][kc], bl0, bl1);
        }
    }
}

// Combined two-operand step: acc += Aa*(vhA+vlA) + Ab*(vhB+vlB).
// Both phases' B-fragment LDGs issue together per kc so the two L2 round
// trips overlap.
template<int NT>
__device__ __forceinline__ void mma_phase2(float acc[][4],
                                           const u32 afA[][4][4],
                                           const u32 afB[][4][4],
                                           const __half* __restrict__ vhA,
                                           const __half* __restrict__ vlA,
                                           const __half* __restrict__ vhB,
                                           const __half* __restrict__ vlB,
                                           int wid, int gid, int tg)
{
#pragma unroll
    for (int kc = 0; kc < 4; ++kc) {
        u32 ah0 = 0u, ah1 = 0u, al0 = 0u, al1 = 0u;
        u32 bh0 = 0u, bh1 = 0u, bl0 = 0u, bl1 = 0u;
        if (gid == 0) {
            const int k0 = wid * 64 + kc * 16 + 2 * tg;
            ah0 = *(const u32*)(vhA + k0); ah1 = *(const u32*)(vhA + k0 + 8);
            al0 = *(const u32*)(vlA + k0); al1 = *(const u32*)(vlA + k0 + 8);
            bh0 = *(const u32*)(vhB + k0); bh1 = *(const u32*)(vhB + k0 + 8);
            bl0 = *(const u32*)(vlB + k0); bl1 = *(const u32*)(vlB + k0 + 8);
        }
#pragma unroll
        for (int mt = 0; mt < NT; ++mt) {
            mma_one(acc[mt], afA[mt][kc], ah0, ah1);
        }
#pragma unroll
        for (int mt = 0; mt < NT; ++mt) {
            mma_one(acc[mt], afA[mt][kc], al0, al1);
        }
#pragma unroll
        for (int mt = 0; mt < NT; ++mt) {
            mma_one(acc[mt], afB[mt][kc], bh0, bh1);
        }
#pragma unroll
        for (int mt = 0; mt < NT; ++mt) {
            mma_one(acc[mt], afB[mt][kc], bl0, bl1);
        }
    }
}

// Column-0 results live in lanes with tg==0: acc[mt][0] = row 16mt+gid,
// acc[mt][2] = row 16mt+8+gid. sp stride 17 floats dodges bank conflicts.
template<int NT>
__device__ __forceinline__ void store_partials(const float acc[][4],
                                               float* __restrict__ sp,
                                               int wid, int gid, int tg)
{
    if (tg == 0) {
#pragma unroll
        for (int mt = 0; mt < NT; ++mt) {
            sp[(mt * 16 + gid) * 17 + wid]     = acc[mt][0];
            sp[(mt * 16 + 8 + gid) * 17 + wid] = acc[mt][2];
        }
    }
}

// ---- Pre-kernel: gx0 precompute + counter init (block 0). ----
__global__ void gx0_kernel(const float* __restrict__ x,
                           const float* __restrict__ wih0,
                           const float* __restrict__ bih0,
                           const float* __restrict__ bhh0)
{
    if (blockIdx.x == 0 && threadIdx.x < 32) g_ctr[threadIdx.x] = 0ULL;
    int idx = blockIdx.x * blockDim.x + threadIdx.x;
    if (idx >= T_STEPS * GDIM) return;
    int t = idx >> 12, rp = idx & 4095;
    int j = rp >> 2, gate = rp & 3;
    int R = (gate << 10) + j;
    const float* w  = wih0 + R * IN_DIM;
    const float* xv = x + t * IN_DIM;
    float a = bih0[R] + bhh0[R];
#pragma unroll
    for (int q = 0; q < IN_DIM; ++q) {
        a = fmaf(w[q], xv[q], a);
    }
    g_gx0[idx] = a;
}

__global__ void __launch_bounds__(NTHR, 1)
lstm_kernel(const float* __restrict__ whh0,
            const float* __restrict__ wih1, const float* __restrict__ whh1,
            const float* __restrict__ bih1, const float* __restrict__ bhh1,
            const float* __restrict__ wlin, const float* __restrict__ blin,
            float* __restrict__ out)
{
    __shared__ float sp[80 * 17];
    __shared__ float sb[80];
    __shared__ float sg[80];
    __shared__ float sc[32];
    __shared__ float sred[16];

    u64* c0 = &g_ctr[0];
    u64* c1 = &g_ctr[16];

    const int tid  = threadIdx.x;
    const int wid  = tid >> 5;          // 0..15
    const int lane = tid & 31;
    const int gid  = lane >> 2;
    const int tg   = lane & 3;
    const int bid  = blockIdx.x;
    const bool isL0 = (bid < NC0);
    const int lb = isL0 ? bid : (bid - NC0);
    const int np = isL0 ? NC0 : NC1;
    const int j0 = lb * HDIM / np;
    const int j1 = (lb + 1) * HDIM / np;
    const int nj = j1 - j0;
    const int nrows = nj * 4;

    if (isL0) {
        // ================= Layer 0 chain (R8-identical) =================
        u32 af0[5][4][4];
        load_frags<5>(af0, whh0, j0, nrows, wid, gid, tg);
        __syncthreads();

        for (int t = 0; t < T_STEPS; ++t) {
            // Prefetch this step's input-gate contribution early (off-path).
            float4 gx = make_float4(0.f, 0.f, 0.f, 0.f);
            if (tid < nj) {
                gx = __ldg((const float4*)(g_gx0 + ((size_t)t << 12) +
                                           (size_t)(j0 + tid) * 4));
            }
            if (t > 0) {
                if (tid == 0) wait_ge(c0, (u64)NC0 * (u64)t);
                __syncthreads();
            }
            float acc[5][4];
#pragma unroll
            for (int mt = 0; mt < 5; ++mt) {
#pragma unroll
                for (int i = 0; i < 4; ++i) acc[mt][i] = 0.f;
            }
            if (t > 0) {
                mma_phase<5>(acc, af0,
                             g_h0h + (size_t)(t - 1) * HDIM,
                             g_h0l + (size_t)(t - 1) * HDIM, wid, gid, tg);
            }
            store_partials<5>(acc, sp, wid, gid, tg);
            __syncthreads();
            if (tid < 80) {
                float s = 0.f;
#pragma unroll
                for (int w = 0; w < 16; ++w) s += sp[tid * 17 + w];
                sg[tid] = s;
            }
            __syncthreads();
            if (wid == 0) {
                if (tid < nj) {
                    float gi = sg[tid*4+0] + gx.x, gf = sg[tid*4+1] + gx.y;
                    float gc = sg[tid*4+2] + gx.z, go = sg[tid*4+3] + gx.w;
                    float i_ = fsig(gi), f_ = fsig(gf);
                    float ci = ftanh_(gc), o_ = fsig(go);
                    float cp = (t == 0) ? 0.f : sc[tid];
                    float c  = fmaf(f_, cp, i_ * ci);
                    sc[tid] = c;
                    float h = o_ * ftanh_(c);
                    __half hh = __float2half(h);
                    __half hl = __float2half(h - __half2float(hh));
                    g_h0h[(size_t)t * HDIM + j0 + tid] = hh;
                    g_h0l[(size_t)t * HDIM + j0 + tid] = hl;
                }
                __syncwarp();                       // orders all warp-0 h stores
                if (lane == 0) red_release(c0);     // ONE release per CTA per step
            }
        }
    } else {
        // ======== Layer 1 chain: fused wait + combined A/B MMA ========
        u32 afA[3][4][4], afB[3][4][4];
        load_frags<3>(afA, wih1, j0, nrows, wid, gid, tg);
        load_frags<3>(afB, whh1, j0, nrows, wid, gid, tg);
        for (int r = tid; r < 80; r += NTHR) sb[r] = 0.f;
        __syncthreads();
        for (int lr = tid; lr < nrows; lr += NTHR) {
            int R = ((lr & 3) << 10) + j0 + (lr >> 2);
            sb[lr] = bih1[R] + bhh1[R];
        }
        __syncthreads();

        for (int t = 0; t < T_STEPS; ++t) {
            // One poll pass + ONE barrier per step; phases A and B run
            // back-to-back with overlapped B-fragment loads.
            if (tid == 0) {
                wait_ge(c0, (u64)NC0 * (u64)(t + 1));      // h0[t] ready
                if (t > 0) wait_ge(c1, (u64)NC1 * (u64)t); // h1[t-1] ready
            }
            __syncthreads();
            float acc[3][4];
#pragma unroll
            for (int mt = 0; mt < 3; ++mt) {
#pragma unroll
                for (int i = 0; i < 4; ++i) acc[mt][i] = 0.f;
            }
            if (t > 0) {
                mma_phase2<3>(acc, afA, afB,
                              g_h0h + (size_t)t * HDIM,
                              g_h0l + (size_t)t * HDIM,
                              g_h1h + (size_t)(t - 1) * HDIM,
                              g_h1l + (size_t)(t - 1) * HDIM, wid, gid, tg);
            } else {
                mma_phase<3>(acc, afA, g_h0h, g_h0l, wid, gid, tg);
            }
            store_partials<3>(acc, sp, wid, gid, tg);
            __syncthreads();
            if (tid < 48) {
                float s = sb[tid];
#pragma unroll
                for (int w = 0; w < 16; ++w) s += sp[tid * 17 + w];
                sg[tid] = s;
            }
            __syncthreads();
            if (wid == 0) {
                if (tid < nj) {
                    float gi = sg[tid*4+0], gf = sg[tid*4+1];
                    float gc = sg[tid*4+2], go = sg[tid*4+3];
                    float i_ = fsig(gi), f_ = fsig(gf);
                    float ci = ftanh_(gc), o_ = fsig(go);
                    float cp = (t == 0) ? 0.f : sc[tid];
                    float c  = fmaf(f_, cp, i_ * ci);
                    sc[tid] = c;
                    float h = o_ * ftanh_(c);
                    __half hh = __float2half(h);
                    __half hl = __float2half(h - __half2float(hh));
                    g_h1h[(size_t)t * HDIM + j0 + tid] = hh;
                    g_h1l[(size_t)t * HDIM + j0 + tid] = hl;
                }
                __syncwarp();
                if (lane == 0) red_release(c1);
            }
        }

        // ---- Final linear (first L1 CTA) ----
        if (bid == NC0) {
            if (tid == 0) wait_ge(c1, (u64)NC1 * (u64)T_STEPS);
            __syncthreads();
            const __half* hh = g_h1h + (size_t)(T_STEPS - 1) * HDIM;
            const __half* hl = g_h1l + (size_t)(T_STEPS - 1) * HDIM;
            float p = 0.f;
            for (int k = tid; k < HDIM; k += NTHR) {
                p = fmaf(__half2float(hh[k]) + __half2float(hl[k]), wlin[k], p);
            }
#pragma unroll
            for (int off = 16; off; off >>= 1) {
                p += __shfl_xor_sync(0xffffffffu, p, off);
            }
            if (lane == 0) sred[wid] = p;
            __syncthreads();
            if (tid == 0) {
                float sres = blin[0];
#pragma unroll
                for (int w = 0; w < 16; ++w) sres += sred[w];
                out[0] = sres;
            }
        }
    }
}

extern "C" void kernel_launch(void* const* d_in, const int* in_sizes, int n_in,
                              void* d_out, int out_size)
{
    gx0_kernel<<<(T_STEPS * GDIM + 255) / 256, 256>>>(
        (const float*)d_in[0], (const float*)d_in[1],
        (const float*)d_in[3], (const float*)d_in[4]);
    lstm_kernel<<<NCTA, NTHR>>>(
        (const float*)d_in[2],                        // w_hh0
        (const float*)d_in[5], (const float*)d_in[6], // w_ih1, w_hh1
        (const float*)d_in[7], (const float*)d_in[8], // b_ih1, b_hh1
        (const float*)d_in[9], (const float*)d_in[10],
        (float*)d_out);
}

// round 13
// speedup vs baseline: 1.0841x; 1.0841x over previous
#include <cuda_runtime.h>
#include <cuda_fp16.h>
#include <cstdint>

#define T_STEPS 8192
#define HDIM    1024
#define IN_DIM  9
#define GDIM    (4 * HDIM)
#define NC0     52          // layer-0 CTAs: nj<=20, 80 rows = 5 m-tiles
#define NC1     86          // layer-1 CTAs: nj<=12, 48 rows = 3 m-tiles
#define NCTA    (NC0 + NC1)
#define NTHR    512         // 16 warps: warp w owns K range [64w, 64w+64)

typedef unsigned int u32;
typedef unsigned long long u64;

// Persistent device scratch. h stored as pre-split fp16 hi/lo pairs so the
// MMA consumes (hi + lo) ~= fp32 h with no conversion on the consumer path.
__device__ __align__(16) float  g_gx0[(size_t)T_STEPS * GDIM]; // W_ih0.x + b, [t][j*4+gate]
__device__ __align__(16) __half g_h0h[(size_t)T_STEPS * HDIM];
__device__ __align__(16) __half g_h0l[(size_t)T_STEPS * HDIM];
__device__ __align__(16) __half g_h1h[(size_t)T_STEPS * HDIM];
__device__ __align__(16) __half g_h1l[(size_t)T_STEPS * HDIM];
__device__ u64 g_ctr[32];                                      // [0]=c0, [16]=c1

__device__ __forceinline__ float fsig(float x) {
    return __fdividef(1.0f, 1.0f + __expf(-x));
}
__device__ __forceinline__ float ftanh_(float x) {
    float a = fabsf(x);
    float e = __expf(-2.0f * a);
    return copysignf(__fdividef(1.0f - e, 1.0f + e), x);
}
__device__ __forceinline__ u64 ld_acquire(const u64* p) {
    u64 v;
    asm volatile("ld.acquire.gpu.global.u64 %0, [%1];" : "=l"(v) : "l"(p) : "memory");
    return v;
}
__device__ __forceinline__ void wait_ge(const u64* p, u64 tgt) {
    while (ld_acquire(p) < tgt) { }
}
__device__ __forceinline__ void red_release(u64* p) {
    asm volatile("red.release.gpu.global.add.u64 [%0], 1;" :: "l"(p) : "memory");
}

__device__ __forceinline__ void mma_one(float* acc, const u32* a, u32 b0, u32 b1) {
    asm volatile(
        "mma.sync.aligned.m16n8k16.row.col.f32.f16.f16.f32 "
        "{%0,%1,%2,%3},{%4,%5,%6,%7},{%8,%9},{%0,%1,%2,%3};"
        : "+f"(acc[0]), "+f"(acc[1]), "+f"(acc[2]), "+f"(acc[3])
        : "r"(a[0]), "r"(a[1]), "r"(a[2]), "r"(a[3]), "r"(b0), "r"(b1));
}

// ---- Load persistent A fragments (m16n8k16 row-major A) from fp32 weights.
// Warp w (of 16) owns K range [64w, 64w+64) = 4 k16 chunks. Local row
// lr = jl*4+gate, global weight row R = gate*HDIM + j0 + jl (gate order i,f,g,o).
// A-frag map: a0=A[gid][2tg..+1], a1=A[gid+8][..], a2=A[gid][2tg+8..+9], a3=A[gid+8][..].
template<int NT>
__device__ __forceinline__ void load_frags(u32 af[][4][4],
                                           const float* __restrict__ W,
                                           int j0, int nrows,
                                           int wid, int gid, int tg)
{
#pragma unroll
    for (int mt = 0; mt < NT; ++mt) {
#pragma unroll
        for (int kc = 0; kc < 4; ++kc) {
            const int k0 = wid * 64 + kc * 16;
#pragma unroll
            for (int i = 0; i < 4; ++i) {
                const int lr = mt * 16 + ((i & 1) ? 8 : 0) + gid;
                const int c  = k0 + 2 * tg + ((i & 2) ? 8 : 0);
                u32 v = 0u;
                if (lr < nrows) {
                    const int jl = lr >> 2, gate = lr & 3;
                    const float2 w2 = *(const float2*)(W +
                        ((size_t)((gate << 10) + j0 + jl) << 10) + c);
                    const __half2 h2 = __floats2half2_rn(w2.x, w2.y);
                    v = *(const u32*)&h2;
                }
                af[mt][kc][i] = v;
            }
        }
    }
}

// ---- One matvec phase: acc += A * vh + A * vl (pre-split hi/lo fp16 vectors).
// B col 0 = v, cols 1-7 = 0. B-frag map: b0 = v[k0+2tg..+1] (col gid==0 only),
// b1 = v[k0+2tg+8..+9].
template<int NT>
__device__ __forceinline__ void mma_phase(float acc[][4],
                                          const u32 af[][4][4],
                                          const __half* __restrict__ vh,
                                          const __half* __restrict__ vl,
                                          int wid, int gid, int tg)
{
#pragma unroll
    for (int kc = 0; kc < 4; ++kc) {
        u32 bh0 = 0u, bh1 = 0u, bl0 = 0u, bl1 = 0u;
        if (gid == 0) {
            const int k0 = wid * 64 + kc * 16 + 2 * tg;
            bh0 = *(const u32*)(vh + k0);
            bh1 = *(const u32*)(vh + k0 + 8);
            bl0 = *(const u32*)(vl + k0);
            bl1 = *(const u32*)(vl + k0 + 8);
        }
#pragma unroll
        for (int mt = 0; mt < NT; ++mt) {
            mma_one(acc[mt], af[mt][kc], bh0, bh1);
        }
#pragma unroll
        for (int mt = 0; mt < NT; ++mt) {
            mma_one(acc[mt], af[mt][kc], bl0, bl1);
        }
    }
}

// Column-0 results live in lanes with tg==0: acc[mt][0] = row 16mt+gid,
// acc[mt][2] = row 16mt+8+gid. sp stride 17 floats dodges bank conflicts.
template<int NT>
__device__ __forceinline__ void store_partials(const float acc[][4],
                                               float* __restrict__ sp,
                                               int wid, int gid, int tg)
{
    if (tg == 0) {
#pragma unroll
        for (int mt = 0; mt < NT; ++mt) {
            sp[(mt * 16 + gid) * 17 + wid]     = acc[mt][0];
            sp[(mt * 16 + 8 + gid) * 17 + wid] = acc[mt][2];
        }
    }
}

// ---- Pre-kernel: gx0[t][j*4+gate] = W_ih0[R].x[t] + b_ih0[R] + b_hh0[R]. ----
__global__ void gx0_kernel(const float* __restrict__ x,
                           const float* __restrict__ wih0,
                           const float* __restrict__ bih0,
                           const float* __restrict__ bhh0)
{
    int idx = blockIdx.x * blockDim.x + threadIdx.x;
    if (idx >= T_STEPS * GDIM) return;
    int t = idx >> 12, rp = idx & 4095;
    int j = rp >> 2, gate = rp & 3;
    int R = (gate << 10) + j;
    const float* w  = wih0 + R * IN_DIM;
    const float* xv = x + t * IN_DIM;
    float a = bih0[R] + bhh0[R];
#pragma unroll
    for (int q = 0; q < IN_DIM; ++q) {
        a = fmaf(w[q], xv[q], a);
    }
    g_gx0[idx] = a;
}

__global__ void init_kernel() {
    if (threadIdx.x < 32) g_ctr[threadIdx.x] = 0ULL;
}

__global__ void __launch_bounds__(NTHR, 1)
lstm_kernel(const float* __restrict__ whh0,
            const float* __restrict__ wih1, const float* __restrict__ whh1,
            const float* __restrict__ bih1, const float* __restrict__ bhh1,
            const float* __restrict__ wlin, const float* __restrict__ blin,
            float* __restrict__ out)
{
    __shared__ float sp[80 * 17];
    __shared__ float sb[80];
    __shared__ float sg[80];
    __shared__ float sc[32];
    __shared__ float sred[16];

    u64* c0 = &g_ctr[0];
    u64* c1 = &g_ctr[16];

    const int tid  = threadIdx.x;
    const int wid  = tid >> 5;          // 0..15
    const int lane = tid & 31;
    const int gid  = lane >> 2;
    const int tg   = lane & 3;
    const int bid  = blockIdx.x;
    const bool isL0 = (bid < NC0);
    const int lb = isL0 ? bid : (bid - NC0);
    const int np = isL0 ? NC0 : NC1;
    const int j0 = lb * HDIM / np;
    const int j1 = (lb + 1) * HDIM / np;
    const int nj = j1 - j0;
    const int nrows = nj * 4;

    if (isL0) {
        // ================= Layer 0 chain =================
        u32 af0[5][4][4];
        load_frags<5>(af0, whh0, j0, nrows, wid, gid, tg);
        __syncthreads();

        for (int t = 0; t < T_STEPS; ++t) {
            // Prefetch this step's input-gate contribution (DRAM) early.
            float4 gx = make_float4(0.f, 0.f, 0.f, 0.f);
            if (tid < nj) {
                gx = __ldg((const float4*)(g_gx0 + ((size_t)t << 12) +
                                           (size_t)(j0 + tid) * 4));
            }
            if (t > 0) {
                if (tid == 0) wait_ge(c0, (u64)NC0 * (u64)t);
                __syncthreads();
            }
            float acc[5][4];
#pragma unroll
            for (int mt = 0; mt < 5; ++mt) {
#pragma unroll
                for (int i = 0; i < 4; ++i) acc[mt][i] = 0.f;
            }
            if (t > 0) {
                mma_phase<5>(acc, af0,
                             g_h0h + (size_t)(t - 1) * HDIM,
                             g_h0l + (size_t)(t - 1) * HDIM, wid, gid, tg);
            }
            store_partials<5>(acc, sp, wid, gid, tg);
            __syncthreads();
            if (tid < 80) {
                float s = 0.f;
#pragma unroll
                for (int w = 0; w < 16; ++w) s += sp[tid * 17 + w];
                sg[tid] = s;
            }
            __syncthreads();
            if (wid == 0) {
                if (tid < nj) {
                    float gi = sg[tid*4+0] + gx.x, gf = sg[tid*4+1] + gx.y;
                    float gc = sg[tid*4+2] + gx.z, go = sg[tid*4+3] + gx.w;
                    float i_ = fsig(gi), f_ = fsig(gf);
                    float ci = ftanh_(gc), o_ = fsig(go);
                    float cp = (t == 0) ? 0.f : sc[tid];
                    float c  = fmaf(f_, cp, i_ * ci);
                    sc[tid] = c;
                    float h = o_ * ftanh_(c);
                    __half hh = __float2half(h);
                    __half hl = __float2half(h - __half2float(hh));
                    g_h0h[(size_t)t * HDIM + j0 + tid] = hh;
                    g_h0l[(size_t)t * HDIM + j0 + tid] = hl;
                }
                __syncwarp();                       // orders all warp-0 h stores
                if (lane == 0) red_release(c0);     // ONE release per CTA per step
            }
        }
    } else {
        // ================= Layer 1 chain =================
        u32 afA[3][4][4], afB[3][4][4];
        load_frags<3>(afA, wih1, j0, nrows, wid, gid, tg);
        load_frags<3>(afB, whh1, j0, nrows, wid, gid, tg);
        for (int r = tid; r < 80; r += NTHR) sb[r] = 0.f;
        __syncthreads();
        for (int lr = tid; lr < nrows; lr += NTHR) {
            int R = ((lr & 3) << 10) + j0 + (lr >> 2);
            sb[lr] = bih1[R] + bhh1[R];
        }
        __syncthreads();

        for (int t = 0; t < T_STEPS; ++t) {
            // Phase A: W_ih1 . h0[t]  (L0 runs ahead; off the h1 critical path)
            if (tid == 0) wait_ge(c0, (u64)NC0 * (u64)(t + 1));
            __syncthreads();
            float acc[3][4];
#pragma unroll
            for (int mt = 0; mt < 3; ++mt) {
#pragma unroll
                for (int i = 0; i < 4; ++i) acc[mt][i] = 0.f;
            }
            mma_phase<3>(acc, afA,
                         g_h0h + (size_t)t * HDIM,
                         g_h0l + (size_t)t * HDIM, wid, gid, tg);

            // Phase B: W_hh1 . h1[t-1]
            if (t > 0) {
                if (tid == 0) wait_ge(c1, (u64)NC1 * (u64)t);
                __syncthreads();
                mma_phase<3>(acc, afB,
                             g_h1h + (size_t)(t - 1) * HDIM,
                             g_h1l + (size_t)(t - 1) * HDIM, wid, gid, tg);
            }
            store_partials<3>(acc, sp, wid, gid, tg);
            __syncthreads();
            if (tid < 48) {
                float s = sb[tid];
#pragma unroll
                for (int w = 0; w < 16; ++w) s += sp[tid * 17 + w];
                sg[tid] = s;
            }
            __syncthreads();
            if (wid == 0) {
                if (tid < nj) {
                    float gi = sg[tid*4+0], gf = sg[tid*4+1];
                    float gc = sg[tid*4+2], go = sg[tid*4+3];
                    float i_ = fsig(gi), f_ = fsig(gf);
                    float ci = ftanh_(gc), o_ = fsig(go);
                    float cp = (t == 0) ? 0.f : sc[tid];
                    float c  = fmaf(f_, cp, i_ * ci);
                    sc[tid] = c;
                    float h = o_ * ftanh_(c);
                    __half hh = __float2half(h);
                    __half hl = __float2half(h - __half2float(hh));
                    g_h1h[(size_t)t * HDIM + j0 + tid] = hh;
                    g_h1l[(size_t)t * HDIM + j0 + tid] = hl;
                }
                __syncwarp();
                if (lane == 0) red_release(c1);
            }
        }

        // ---- Final linear (first L1 CTA) ----
        if (bid == NC0) {
            if (tid == 0) wait_ge(c1, (u64)NC1 * (u64)T_STEPS);
            __syncthreads();
            const __half* hh = g_h1h + (size_t)(T_STEPS - 1) * HDIM;
            const __half* hl = g_h1l + (size_t)(T_STEPS - 1) * HDIM;
            float p = 0.f;
            for (int k = tid; k < HDIM; k += NTHR) {
                p = fmaf(__half2float(hh[k]) + __half2float(hl[k]), wlin[k], p);
            }
#pragma unroll
            for (int off = 16; off; off >>= 1) {
                p += __shfl_xor_sync(0xffffffffu, p, off);
            }
            if (lane == 0) sred[wid] = p;
            __syncthreads();
            if (tid == 0) {
                float sres = blin[0];
#pragma unroll
                for (int w = 0; w < 16; ++w) sres += sred[w];
                out[0] = sres;
            }
        }
    }
}

extern "C" void kernel_launch(void* const* d_in, const int* in_sizes, int n_in,
                              void* d_out, int out_size)
{
    init_kernel<<<1, 32>>>();
    gx0_kernel<<<(T_STEPS * GDIM + 255) / 256, 256>>>(
        (const float*)d_in[0], (const float*)d_in[1],
        (const float*)d_in[3], (const float*)d_in[4]);
    lstm_kernel<<<NCTA, NTHR>>>(
        (const float*)d_in[2],                        // w_hh0
        (const float*)d_in[5], (const float*)d_in[6], // w_ih1, w_hh1
        (const float*)d_in[7], (const float*)d_in[8], // b_ih1, b_hh1
        (const float*)d_in[9], (const float*)d_in[10],
        (float*)d_out);
}